// round 11
// baseline (speedup 1.0000x reference)
#include <cuda_runtime.h>

// Static problem shapes (see reference)
#define BATCH 128
#define RR    64      // regions == words
#define DD    128     // feature dim
#define KC    64      // k-chunk for staging

// A staged duplicated: [128 m][2*KC floats], row stride PADA2 (even, +2 pad)
#define PADA2 130
#define SA_FLOATS (128 * PADA2)            // 16640
// B staged k-major XOR-swizzled: [KC k][128 n], no pad (swizzle kills conflicts)
#define SB_OFF    SA_FLOATS                // float offset (byte 66560, 16B aligned)
#define SB_FLOATS (KC * 128)               // 8192
// sims tile [128][PADS]; odd pad -> conflict-free rows AND columns
#define PADS 133
#define SMEM_FLOATS (SA_FLOATS + SB_FLOATS)   // 24832 > 128*133 = 17024
#define SMEM_BYTES  (SMEM_FLOATS * 4)         // 99328

__device__ __forceinline__ unsigned long long ffma2(
    unsigned long long a, unsigned long long b, unsigned long long c) {
    unsigned long long d;
    asm("fma.rn.f32x2 %0, %1, %2, %3;" : "=l"(d) : "l"(a), "l"(b), "l"(c));
    return d;
}

__device__ __forceinline__ float warp_fsum(float s) {
#pragma unroll
    for (int o = 16; o > 0; o >>= 1)
        s += __shfl_xor_sync(0xffffffffu, s, o);
    return s;
}

// Sparsemax line of 64 values held as (z0, z1) across 32 lanes.
// Returns sum_j max(z_j - tau, 0) * z_j (broadcast to all lanes).
// tau via Michelot fixed point: tau <- (sum_{z>tau} z - 1)/|{z>tau}|;
// support count uses REDUX.SUM (u32), float sum uses shfl tree.
__device__ __forceinline__ float sparse_line_val(float z0, float z1) {
    float tau = (warp_fsum(z0 + z1) - 1.0f) * (1.0f / 64.0f);
    int cprev = 64;
#pragma unroll 1
    for (int it = 0; it < 64; ++it) {
        float s2 = 0.0f;
        int   c2 = 0;
        if (z0 > tau) { s2 += z0; ++c2; }
        if (z1 > tau) { s2 += z1; ++c2; }
        s2 = warp_fsum(s2);
        c2 = __reduce_add_sync(0xffffffffu, (unsigned)c2);
        if (c2 == cprev) break;
        tau = (s2 - 1.0f) / (float)c2;
        cprev = c2;
    }
    return warp_fsum(fmaxf(z0 - tau, 0.0f) * z0 + fmaxf(z1 - tau, 0.0f) * z1);
}

extern __shared__ float smem[];

__global__ __launch_bounds__(256, 2)
void select_kernel(const float* __restrict__ imgs,
                   const float* __restrict__ caps,
                   const int*   __restrict__ img_lens,
                   const int*   __restrict__ cap_lens,
                   float*       __restrict__ out)
{
    const int t0 = blockIdx.x * 2;   // caption pair base
    const int i0 = blockIdx.y * 2;   // image pair base
    const int tid = threadIdx.x;

    float* sAd = smem;               // duplicated A: [m][2k] {v,v}
    float* sB  = smem + SB_OFF;      // swizzled k-major B
    float* sS  = smem;               // sims [128][PADS], reuses staging region
    __shared__ float s_acc[8];       // v2t[4], t2v[4]
    __shared__ int   s_len[4];

    if (tid < 8) s_acc[tid] = 0.0f;
    if (tid == 0) {
        s_len[0] = img_lens[i0];
        s_len[1] = img_lens[i0 + 1];
        s_len[2] = cap_lens[t0];
        s_len[3] = cap_lens[t0 + 1];
    }

    const float* gA = imgs + (size_t)i0 * (RR * DD);   // 2 images: 128 rows
    const float* gB = caps + (size_t)t0 * (RR * DD);   // 2 captions: 128 rows

    const int ty = tid >> 4, tx = tid & 15;
    const int m0 = ty * 8, n0 = tx * 8;

    unsigned long long acc2[8][4];   // (n, n+1) packed fp32 pairs
#pragma unroll
    for (int a = 0; a < 8; ++a)
#pragma unroll
        for (int b = 0; b < 4; ++b) acc2[a][b] = 0ull;

    // ================= 128x128x128 GEMM, two k-chunks, FFMA2 =================
#pragma unroll 1
    for (int kc = 0; kc < 2; ++kc) {
        const int kb = kc * KC;

        // Stage A duplicated {v,v}: coalesced LDG, conflict-free STS.64
#pragma unroll
        for (int e = tid; e < 128 * KC; e += 256) {
            const int m = e >> 6, k = e & 63;
            const float v = gA[m * DD + kb + k];
            *(float2*)(sAd + m * PADA2 + 2 * k) = make_float2(v, v);
        }
        // Stage B k-major with XOR swizzle: float4 LDG, 4 scalar STS (2-way)
#pragma unroll
        for (int e = tid; e < 128 * (KC / 4); e += 256) {
            const int n = e >> 4, kg = e & 15;
            const float4 v = *(const float4*)(gB + n * DD + kb + 4 * kg);
            const int grp = ((n >> 2) ^ (kg & 7)) << 2;
            const int lo  = n & 3;
            float* p = sB + 4 * kg * 128 + grp + lo;
            p[0]       = v.x;
            p[128]     = v.y;
            p[2 * 128] = v.z;
            p[3 * 128] = v.w;
        }
        __syncthreads();

#pragma unroll 4
        for (int k = 0; k < KC; ++k) {
            // a-operands: pre-duplicated pairs, one LDS.64 each (broadcast)
            unsigned long long ar2[8];
#pragma unroll
            for (int j = 0; j < 8; ++j)
                ar2[j] = *(const unsigned long long*)(sAd + (m0 + j) * PADA2 + 2 * k);
            // b-operands: two LDS.128 -> four (n,n+1) pairs, swizzled address
            const int s = (k >> 2) & 7;
            const float* brow = sB + k * 128;
            const ulonglong2 b0 = *(const ulonglong2*)(brow + ((((n0 >> 2)    ) ^ s) << 2));
            const ulonglong2 b1 = *(const ulonglong2*)(brow + ((((n0 >> 2) + 1) ^ s) << 2));
            const unsigned long long br2[4] = {b0.x, b0.y, b1.x, b1.y};
#pragma unroll
            for (int a = 0; a < 8; ++a)
#pragma unroll
                for (int b = 0; b < 4; ++b)
                    acc2[a][b] = ffma2(ar2[a], br2[b], acc2[a][b]);
        }
        __syncthreads();   // chunk consumed; buffers reusable
    }

    // ================= Masked sims -> smem =================
    const int il[2] = {s_len[0], s_len[1]};
    const int cl[2] = {s_len[2], s_len[3]};
#pragma unroll
    for (int a = 0; a < 8; ++a) {
        const int m = m0 + a;
        const int pi = m >> 6, r = m & 63;
        const bool rok = (r < il[pi]);
#pragma unroll
        for (int b = 0; b < 4; ++b) {
            const float2 v2 = *(const float2*)&acc2[a][b];
            const int n = n0 + 2 * b;
            const int pt = n >> 6;
            const int w0 = n & 63;
            sS[m * PADS + n]     = (rok && (w0     < cl[pt])) ? v2.x : -1.0f;
            sS[m * PADS + n + 1] = (rok && (w0 + 1 < cl[pt])) ? v2.y : -1.0f;
        }
    }
    __syncthreads();

    // ================= Sparsemax: 4 pairs x (64 rows + 64 cols) =================
    const int wid = tid >> 5, lane = tid & 31;
    float pv[8] = {0, 0, 0, 0, 0, 0, 0, 0};   // v2t[pair], t2v[pair]

#pragma unroll 1
    for (int L = wid; L < 512; L += 8) {
        if (L < 256) {                        // rows: region -> word
            const int pair = L >> 6, r = L & 63;
            const int pi = pair >> 1, pt = pair & 1;
            if (r < il[pi]) {
                const float* row = sS + (pi * 64 + r) * PADS + pt * 64;
                pv[pair] += sparse_line_val(row[lane], row[lane + 32]);
            }
        } else {                              // cols: word -> region
            const int idx = L - 256;
            const int pair = idx >> 6, w = idx & 63;
            const int pi = pair >> 1, pt = pair & 1;
            if (w < cl[pt]) {
                const float* col = sS + (pi * 64) * PADS + pt * 64 + w;
                pv[4 + pair] += sparse_line_val(col[lane * PADS],
                                                col[(lane + 32) * PADS]);
            }
        }
    }
    if (lane == 0) {
#pragma unroll
        for (int q = 0; q < 8; ++q)
            if (pv[q] != 0.0f) atomicAdd(&s_acc[q], pv[q]);
    }
    __syncthreads();

    if (tid < 4) {
        const int pi = tid >> 1, pt = tid & 1;
        out[(i0 + pi) * BATCH + (t0 + pt)] =
            0.5f * (s_acc[tid] / (float)il[pi] + s_acc[4 + tid] / (float)cl[pt]);
    }
}

extern "C" void kernel_launch(void* const* d_in, const int* in_sizes, int n_in,
                              void* d_out, int out_size) {
    // metadata order: img_cls, imgs, cap_cls, caps, img_lens, cap_lens
    const float* imgs     = (const float*)d_in[1];
    const float* caps     = (const float*)d_in[3];
    const int*   img_lens = (const int*)  d_in[4];
    const int*   cap_lens = (const int*)  d_in[5];
    float*       out      = (float*)d_out;

    cudaFuncSetAttribute(select_kernel,
                         cudaFuncAttributeMaxDynamicSharedMemorySize,
                         SMEM_BYTES);
    dim3 grid(BATCH / 2, BATCH / 2);
    select_kernel<<<grid, 256, SMEM_BYTES>>>(imgs, caps, img_lens, cap_lens, out);
}

// round 14
// speedup vs baseline: 1.2739x; 1.2739x over previous
#include <cuda_runtime.h>
#include <cuda_bf16.h>
#include <cstdint>

// Static problem shapes
#define BATCH 128
#define DD    128
#define CHUNK 64            // k per staged chunk
#define PADS  133           // sims [128][PADS] f32; odd pad -> conflict-free rows AND cols
#define PITCH 144           // staged row: 64 bf16 = 128B data + 16B pad (36 words == 4 mod 32)

#define OFF_AHI 0           // each buffer: 128 rows x PITCH = 18432 B
#define OFF_ALO 18432
#define OFF_BHI 36864
#define OFF_BLO 55296
#define SMEM_BYTES 73728    // staging 72KB; sims (68096 B) reuses [0,..) after GEMM

__device__ __forceinline__ uint32_t smem_addr_u32(const void* p) {
    uint32_t a;
    asm("{ .reg .u64 t; cvta.to.shared.u64 t, %1; cvt.u32.u64 %0, t; }" : "=r"(a) : "l"(p));
    return a;
}

__device__ __forceinline__ void ldm_x4(uint32_t* a, uint32_t addr) {
    asm volatile("ldmatrix.sync.aligned.m8n8.x4.shared.b16 {%0,%1,%2,%3}, [%4];"
                 : "=r"(a[0]), "=r"(a[1]), "=r"(a[2]), "=r"(a[3]) : "r"(addr));
}

__device__ __forceinline__ void mma16816(float* c, const uint32_t* a,
                                         uint32_t b0, uint32_t b1) {
    asm volatile(
        "mma.sync.aligned.m16n8k16.row.col.f32.bf16.bf16.f32 "
        "{%0,%1,%2,%3}, {%4,%5,%6,%7}, {%8,%9}, {%0,%1,%2,%3};"
        : "+f"(c[0]), "+f"(c[1]), "+f"(c[2]), "+f"(c[3])
        : "r"(a[0]), "r"(a[1]), "r"(a[2]), "r"(a[3]), "r"(b0), "r"(b1));
}

__device__ __forceinline__ float warp_fsum(float s) {
#pragma unroll
    for (int o = 16; o > 0; o >>= 1) s += __shfl_xor_sync(0xffffffffu, s, o);
    return s;
}

// Sparsemax line (64 vals as z0,z1 across 32 lanes): sum_j max(z_j - tau, 0) * z_j.
// tau via Michelot fixed point; u32 REDUX for the support count.
__device__ __forceinline__ float sparse_line_val(float z0, float z1) {
    float tau = (warp_fsum(z0 + z1) - 1.0f) * (1.0f / 64.0f);
    int cprev = 64;
#pragma unroll 1
    for (int it = 0; it < 64; ++it) {
        float s2 = 0.0f; int c2 = 0;
        if (z0 > tau) { s2 += z0; ++c2; }
        if (z1 > tau) { s2 += z1; ++c2; }
        s2 = warp_fsum(s2);
        c2 = __reduce_add_sync(0xffffffffu, (unsigned)c2);
        if (c2 == cprev) break;
        tau = (s2 - 1.0f) / (float)c2;
        cprev = c2;
    }
    return warp_fsum(fmaxf(z0 - tau, 0.0f) * z0 + fmaxf(z1 - tau, 0.0f) * z1);
}

extern __shared__ __align__(1024) char smem[];

__global__ __launch_bounds__(256, 2)
void select_kernel(const float* __restrict__ imgs,
                   const float* __restrict__ caps,
                   const int*   __restrict__ img_lens,
                   const int*   __restrict__ cap_lens,
                   float*       __restrict__ out)
{
    const int t0 = blockIdx.x * 2, i0 = blockIdx.y * 2;
    const int tid = threadIdx.x, wid = tid >> 5, lane = tid & 31;
    const int gid = lane >> 2, tig = lane & 3;
    const uint32_t sbase = smem_addr_u32(smem);

    float* sS = (float*)smem;                  // sims [128][PADS] (reuses staging)
    __shared__ float s_acc[8];                 // v2t[4], t2v[4]
    __shared__ int   s_len[4];

    if (tid < 8) s_acc[tid] = 0.0f;
    if (tid == 0) {
        s_len[0] = img_lens[i0];   s_len[1] = img_lens[i0 + 1];
        s_len[2] = cap_lens[t0];   s_len[3] = cap_lens[t0 + 1];
    }
    __syncthreads();
    const int il[2] = {s_len[0], s_len[1]};
    const int cl[2] = {s_len[2], s_len[3]};

    const float* gA = imgs + (size_t)i0 * (64 * DD);   // 2 images  = 128 rows
    const float* gB = caps + (size_t)t0 * (64 * DD);   // 2 captions = 128 rows

    // fp32 accumulators: warp tile m16 x n128 (16 n-tiles of 8)
    float c[16][4];
#pragma unroll
    for (int nt = 0; nt < 16; ++nt)
#pragma unroll
        for (int q = 0; q < 4; ++q) c[nt][q] = 0.0f;

    const int m0 = wid * 16;
    // ldmatrix addr: lanes 0-7 rows m0..+7 @k0, 8-15 rows +8..+15 @k0,
    // 16-23 rows ..+7 @k8, 24-31 rows +8..+15 @k8
    const uint32_t abase = sbase + (uint32_t)(m0 + (lane & 15)) * PITCH
                                 + (uint32_t)((lane >> 4) << 4);

    // ============ 2 chunks: stage bf16 hi/lo (144B-pitch rows), then HMMA ============
#pragma unroll 1
    for (int kc = 0; kc < 2; ++kc) {
        const int kb = kc * CHUNK;
#pragma unroll 4
        for (int e = tid; e < 4096; e += 256) {          // 128 rows x 32 k-pairs
            const int row = e >> 5, j = e & 31;
            const uint32_t off = (uint32_t)row * PITCH + (uint32_t)j * 4;

            const float2 va = *(const float2*)(gA + row * DD + kb + 2 * j);
            __nv_bfloat16 ah0 = __float2bfloat16(va.x), ah1 = __float2bfloat16(va.y);
            __nv_bfloat162 ahp = __halves2bfloat162(ah0, ah1);
            __nv_bfloat162 alp = __floats2bfloat162_rn(va.x - __bfloat162float(ah0),
                                                       va.y - __bfloat162float(ah1));
            *(uint32_t*)(smem + OFF_AHI + off) = *(uint32_t*)&ahp;
            *(uint32_t*)(smem + OFF_ALO + off) = *(uint32_t*)&alp;

            const float2 vb = *(const float2*)(gB + row * DD + kb + 2 * j);
            __nv_bfloat16 bh0 = __float2bfloat16(vb.x), bh1 = __float2bfloat16(vb.y);
            __nv_bfloat162 bhp = __halves2bfloat162(bh0, bh1);
            __nv_bfloat162 blp = __floats2bfloat162_rn(vb.x - __bfloat162float(bh0),
                                                       vb.y - __bfloat162float(bh1));
            *(uint32_t*)(smem + OFF_BHI + off) = *(uint32_t*)&bhp;
            *(uint32_t*)(smem + OFF_BLO + off) = *(uint32_t*)&blp;
        }
        __syncthreads();

#pragma unroll
        for (int ks = 0; ks < 4; ++ks) {                 // k16 steps within chunk
            uint32_t ah[4], al[4];
            ldm_x4(ah, abase + OFF_AHI + (uint32_t)(ks * 32));
            ldm_x4(al, abase + OFF_ALO + (uint32_t)(ks * 32));
#pragma unroll
            for (int nt = 0; nt < 16; ++nt) {
                // B frag (n-major staging): b0b1 = B[n0+gid][k0+2*tig..], b2b3 = +8k
                const char* bp = smem + (uint32_t)(nt * 8 + gid) * PITCH
                                      + (uint32_t)(ks * 32 + tig * 4);
                const uint32_t bh0 = *(const uint32_t*)(bp + OFF_BHI);
                const uint32_t bh1 = *(const uint32_t*)(bp + OFF_BHI + 16);
                const uint32_t bl0 = *(const uint32_t*)(bp + OFF_BLO);
                const uint32_t bl1 = *(const uint32_t*)(bp + OFF_BLO + 16);
                mma16816(c[nt], ah, bh0, bh1);   // hi*hi
                mma16816(c[nt], ah, bl0, bl1);   // hi*lo
                mma16816(c[nt], al, bh0, bh1);   // lo*hi
            }
        }
        __syncthreads();   // staging consumed; safe to restage / reuse as sims
    }

    // ============ Masked sims -> smem ============
    // C frag: c0,c1 = row gid, cols 2tig,+1 ; c2,c3 = row gid+8
#pragma unroll
    for (int nt = 0; nt < 16; ++nt) {
#pragma unroll
        for (int h = 0; h < 2; ++h) {
            const int m = m0 + gid + h * 8;
            const int pi = m >> 6, r = m & 63;
            const bool rok = (r < il[pi]);
            const int n = nt * 8 + 2 * tig;
            const int pt = n >> 6, w = n & 63;
            sS[m * PADS + n]     = (rok && (w     < cl[pt])) ? c[nt][2 * h]     : -1.0f;
            sS[m * PADS + n + 1] = (rok && (w + 1 < cl[pt])) ? c[nt][2 * h + 1] : -1.0f;
        }
    }
    __syncthreads();

    // ============ Sparsemax: 4 pairs x (64 rows + 64 cols) ============
    float pv[8] = {0, 0, 0, 0, 0, 0, 0, 0};
#pragma unroll 1
    for (int L = wid; L < 512; L += 8) {
        if (L < 256) {                          // rows: region -> word
            const int pair = L >> 6, r = L & 63;
            const int pi = pair >> 1, pt = pair & 1;
            if (r < il[pi]) {
                const float* row = sS + (pi * 64 + r) * PADS + pt * 64;
                pv[pair] += sparse_line_val(row[lane], row[lane + 32]);
            }
        } else {                                // cols: word -> region
            const int idx = L - 256;
            const int pair = idx >> 6, w = idx & 63;
            const int pi = pair >> 1, pt = pair & 1;
            if (w < cl[pt]) {
                const float* col = sS + (pi * 64) * PADS + pt * 64 + w;
                pv[4 + pair] += sparse_line_val(col[lane * PADS], col[(lane + 32) * PADS]);
            }
        }
    }
    if (lane == 0) {
#pragma unroll
        for (int q = 0; q < 8; ++q)
            if (pv[q] != 0.0f) atomicAdd(&s_acc[q], pv[q]);
    }
    __syncthreads();

    if (tid < 4) {
        const int pi = tid >> 1, pt = tid & 1;
        out[(i0 + pi) * BATCH + (t0 + pt)] =
            0.5f * (s_acc[tid] / (float)il[pi] + s_acc[4 + tid] / (float)cl[pt]);
    }
}

extern "C" void kernel_launch(void* const* d_in, const int* in_sizes, int n_in,
                              void* d_out, int out_size) {
    // metadata order: img_cls, imgs, cap_cls, caps, img_lens, cap_lens
    const float* imgs     = (const float*)d_in[1];
    const float* caps     = (const float*)d_in[3];
    const int*   img_lens = (const int*)  d_in[4];
    const int*   cap_lens = (const int*)  d_in[5];
    float*       out      = (float*)d_out;

    cudaFuncSetAttribute(select_kernel,
                         cudaFuncAttributeMaxDynamicSharedMemorySize, SMEM_BYTES);
    dim3 grid(BATCH / 2, BATCH / 2);
    select_kernel<<<grid, 256, SMEM_BYTES>>>(imgs, caps, img_lens, cap_lens, out);
}

// round 16
// speedup vs baseline: 4.0179x; 3.1540x over previous
#include <cuda_runtime.h>
#include <cuda_bf16.h>
#include <cstdint>

// Static problem shapes
#define BATCH 128
#define DD    128
#define CHUNK 64            // k per staged chunk
#define PADS  133           // sims [128][PADS] f32; odd pad -> conflict-free rows AND cols
#define PITCH 144           // staged row: 64 bf16 = 128B data + 16B pad (36 words == 4 mod 32)

#define OFF_AHI 0           // each buffer: 128 rows x PITCH = 18432 B
#define OFF_ALO 18432
#define OFF_BHI 36864
#define OFF_BLO 55296
#define SMEM_BYTES 73728    // staging 72KB; sims (68096 B) reuses [0,..) after GEMM

__device__ __forceinline__ uint32_t smem_addr_u32(const void* p) {
    uint32_t a;
    asm("{ .reg .u64 t; cvta.to.shared.u64 t, %1; cvt.u32.u64 %0, t; }" : "=r"(a) : "l"(p));
    return a;
}

__device__ __forceinline__ void ldm_x4(uint32_t* a, uint32_t addr) {
    asm volatile("ldmatrix.sync.aligned.m8n8.x4.shared.b16 {%0,%1,%2,%3}, [%4];"
                 : "=r"(a[0]), "=r"(a[1]), "=r"(a[2]), "=r"(a[3]) : "r"(addr));
}

__device__ __forceinline__ void mma16816(float* c, const uint32_t* a,
                                         uint32_t b0, uint32_t b1) {
    asm volatile(
        "mma.sync.aligned.m16n8k16.row.col.f32.bf16.bf16.f32 "
        "{%0,%1,%2,%3}, {%4,%5,%6,%7}, {%8,%9}, {%0,%1,%2,%3};"
        : "+f"(c[0]), "+f"(c[1]), "+f"(c[2]), "+f"(c[3])
        : "r"(a[0]), "r"(a[1]), "r"(a[2]), "r"(a[3]), "r"(b0), "r"(b1));
}

__device__ __forceinline__ float warp_fsum(float s) {
#pragma unroll
    for (int o = 16; o > 0; o >>= 1) s += __shfl_xor_sync(0xffffffffu, s, o);
    return s;
}

// Per-thread serial sparsemax over one 64-value line, values cached in registers.
// Returns sum_j max(z_j - tau, 0) * z_j. tau via Michelot fixed point:
// tau <- (sum_{z>tau} z - 1)/|{z>tau}| (support strictly shrinks; terminates).
__device__ __forceinline__ float sparse_line_serial(const float* z, int stride) {
    float v[64];
#pragma unroll
    for (int j = 0; j < 64; ++j) v[j] = z[j * stride];

    float s0 = 0.f, s1 = 0.f, s2 = 0.f, s3 = 0.f;
#pragma unroll
    for (int j = 0; j < 64; j += 4) {
        s0 += v[j]; s1 += v[j + 1]; s2 += v[j + 2]; s3 += v[j + 3];
    }
    float tau = ((s0 + s1) + (s2 + s3) - 1.0f) * (1.0f / 64.0f);
    int cprev = 64;
#pragma unroll 1
    for (int it = 0; it < 64; ++it) {
        float a0 = 0.f, a1 = 0.f, a2 = 0.f, a3 = 0.f;
        int c = 0;
#pragma unroll
        for (int j = 0; j < 64; j += 4) {
            if (v[j]     > tau) { a0 += v[j];     ++c; }
            if (v[j + 1] > tau) { a1 += v[j + 1]; ++c; }
            if (v[j + 2] > tau) { a2 += v[j + 2]; ++c; }
            if (v[j + 3] > tau) { a3 += v[j + 3]; ++c; }
        }
        if (c == cprev) break;
        tau = ((a0 + a1) + (a2 + a3) - 1.0f) / (float)c;
        cprev = c;
    }
    float r0 = 0.f, r1 = 0.f, r2 = 0.f, r3 = 0.f;
#pragma unroll
    for (int j = 0; j < 64; j += 4) {
        r0 += fmaxf(v[j]     - tau, 0.f) * v[j];
        r1 += fmaxf(v[j + 1] - tau, 0.f) * v[j + 1];
        r2 += fmaxf(v[j + 2] - tau, 0.f) * v[j + 2];
        r3 += fmaxf(v[j + 3] - tau, 0.f) * v[j + 3];
    }
    return (r0 + r1) + (r2 + r3);
}

extern __shared__ __align__(1024) char smem[];

__global__ __launch_bounds__(256, 2)
void select_kernel(const float* __restrict__ imgs,
                   const float* __restrict__ caps,
                   const int*   __restrict__ img_lens,
                   const int*   __restrict__ cap_lens,
                   float*       __restrict__ out)
{
    const int t0 = blockIdx.x * 2, i0 = blockIdx.y * 2;
    const int tid = threadIdx.x, wid = tid >> 5, lane = tid & 31;
    const int gid = lane >> 2, tig = lane & 3;
    const uint32_t sbase = smem_addr_u32(smem);

    float* sS = (float*)smem;                  // sims [128][PADS] (reuses staging)
    __shared__ float s_acc[8];                 // v2t[4], t2v[4]
    __shared__ int   s_len[4];

    if (tid < 8) s_acc[tid] = 0.0f;
    if (tid == 0) {
        s_len[0] = img_lens[i0];   s_len[1] = img_lens[i0 + 1];
        s_len[2] = cap_lens[t0];   s_len[3] = cap_lens[t0 + 1];
    }
    __syncthreads();
    const int il[2] = {s_len[0], s_len[1]};
    const int cl[2] = {s_len[2], s_len[3]};

    const float* gA = imgs + (size_t)i0 * (64 * DD);   // 2 images  = 128 rows
    const float* gB = caps + (size_t)t0 * (64 * DD);   // 2 captions = 128 rows

    // fp32 accumulators: warp tile m16 x n128 (16 n-tiles of 8)
    float c[16][4];
#pragma unroll
    for (int nt = 0; nt < 16; ++nt)
#pragma unroll
        for (int q = 0; q < 4; ++q) c[nt][q] = 0.0f;

    const int m0 = wid * 16;
    const uint32_t abase = sbase + (uint32_t)(m0 + (lane & 15)) * PITCH
                                 + (uint32_t)((lane >> 4) << 4);

    // ============ 2 chunks: stage bf16 hi/lo (144B-pitch rows), then HMMA ============
#pragma unroll 1
    for (int kc = 0; kc < 2; ++kc) {
        const int kb = kc * CHUNK;
#pragma unroll 4
        for (int e = tid; e < 4096; e += 256) {          // 128 rows x 32 k-pairs
            const int row = e >> 5, j = e & 31;
            const uint32_t off = (uint32_t)row * PITCH + (uint32_t)j * 4;

            const float2 va = *(const float2*)(gA + row * DD + kb + 2 * j);
            __nv_bfloat16 ah0 = __float2bfloat16(va.x), ah1 = __float2bfloat16(va.y);
            __nv_bfloat162 ahp = __halves2bfloat162(ah0, ah1);
            __nv_bfloat162 alp = __floats2bfloat162_rn(va.x - __bfloat162float(ah0),
                                                       va.y - __bfloat162float(ah1));
            *(uint32_t*)(smem + OFF_AHI + off) = *(uint32_t*)&ahp;
            *(uint32_t*)(smem + OFF_ALO + off) = *(uint32_t*)&alp;

            const float2 vb = *(const float2*)(gB + row * DD + kb + 2 * j);
            __nv_bfloat16 bh0 = __float2bfloat16(vb.x), bh1 = __float2bfloat16(vb.y);
            __nv_bfloat162 bhp = __halves2bfloat162(bh0, bh1);
            __nv_bfloat162 blp = __floats2bfloat162_rn(vb.x - __bfloat162float(bh0),
                                                       vb.y - __bfloat162float(bh1));
            *(uint32_t*)(smem + OFF_BHI + off) = *(uint32_t*)&bhp;
            *(uint32_t*)(smem + OFF_BLO + off) = *(uint32_t*)&blp;
        }
        __syncthreads();

#pragma unroll
        for (int ks = 0; ks < 4; ++ks) {                 // k16 steps within chunk
            uint32_t ah[4], al[4];
            ldm_x4(ah, abase + OFF_AHI + (uint32_t)(ks * 32));
            ldm_x4(al, abase + OFF_ALO + (uint32_t)(ks * 32));
#pragma unroll
            for (int nt = 0; nt < 16; ++nt) {
                const char* bp = smem + (uint32_t)(nt * 8 + gid) * PITCH
                                      + (uint32_t)(ks * 32 + tig * 4);
                const uint32_t bh0 = *(const uint32_t*)(bp + OFF_BHI);
                const uint32_t bh1 = *(const uint32_t*)(bp + OFF_BHI + 16);
                const uint32_t bl0 = *(const uint32_t*)(bp + OFF_BLO);
                const uint32_t bl1 = *(const uint32_t*)(bp + OFF_BLO + 16);
                mma16816(c[nt], ah, bh0, bh1);   // hi*hi
                mma16816(c[nt], ah, bl0, bl1);   // hi*lo
                mma16816(c[nt], al, bh0, bh1);   // lo*hi
            }
        }
        __syncthreads();   // staging consumed; safe to restage / reuse as sims
    }

    // ============ Masked sims -> smem ============
#pragma unroll
    for (int nt = 0; nt < 16; ++nt) {
#pragma unroll
        for (int h = 0; h < 2; ++h) {
            const int m = m0 + gid + h * 8;
            const int pi = m >> 6, r = m & 63;
            const bool rok = (r < il[pi]);
            const int n = nt * 8 + 2 * tig;
            const int pt = n >> 6, w = n & 63;
            sS[m * PADS + n]     = (rok && (w     < cl[pt])) ? c[nt][2 * h]     : -1.0f;
            sS[m * PADS + n + 1] = (rok && (w + 1 < cl[pt])) ? c[nt][2 * h + 1] : -1.0f;
        }
    }
    __syncthreads();

    // ============ Sparsemax: per-thread serial, 1 row line + 1 col line ============
    // Row line t: pair = t>>6 (warp-uniform), r = t&63; elements stride 1.
    {
        const int pair = tid >> 6, r = tid & 63;
        const int pi = pair >> 1, pt = pair & 1;
        float val = 0.0f;
        if (r < il[pi])
            val = sparse_line_serial(sS + (pi * 64 + r) * PADS + pt * 64, 1);
        const float wsum = warp_fsum(val);
        if (lane == 0 && wsum != 0.0f) atomicAdd(&s_acc[pair], wsum);
    }
    // Col line t: pair = t>>6, w = t&63; elements stride PADS.
    {
        const int pair = tid >> 6, w = tid & 63;
        const int pi = pair >> 1, pt = pair & 1;
        float val = 0.0f;
        if (w < cl[pt])
            val = sparse_line_serial(sS + (pi * 64) * PADS + pt * 64 + w, PADS);
        const float wsum = warp_fsum(val);
        if (lane == 0 && wsum != 0.0f) atomicAdd(&s_acc[4 + pair], wsum);
    }
    __syncthreads();

    if (tid < 4) {
        const int pi = tid >> 1, pt = tid & 1;
        out[(i0 + pi) * BATCH + (t0 + pt)] =
            0.5f * (s_acc[tid] / (float)il[pi] + s_acc[4 + tid] / (float)cl[pt]);
    }
}

extern "C" void kernel_launch(void* const* d_in, const int* in_sizes, int n_in,
                              void* d_out, int out_size) {
    // metadata order: img_cls, imgs, cap_cls, caps, img_lens, cap_lens
    const float* imgs     = (const float*)d_in[1];
    const float* caps     = (const float*)d_in[3];
    const int*   img_lens = (const int*)  d_in[4];
    const int*   cap_lens = (const int*)  d_in[5];
    float*       out      = (float*)d_out;

    cudaFuncSetAttribute(select_kernel,
                         cudaFuncAttributeMaxDynamicSharedMemorySize, SMEM_BYTES);
    dim3 grid(BATCH / 2, BATCH / 2);
    select_kernel<<<grid, 256, SMEM_BYTES>>>(imgs, caps, img_lens, cap_lens, out);
}